// round 9
// baseline (speedup 1.0000x reference)
#include <cuda_runtime.h>
#include <cuda_bf16.h>
#include <stdint.h>

// B=1024, K=4, E=16, H=2048, I=2048 (fp32 in/out)
#define NE   16
#define HD   2048
#define ID   2048
#define I2D  4096
#define NP   4096
#define BM   128
#define BN   128
#define KT   32            // k elements per smem stage
#define NIT  64            // 2048 / 32
#define SROW 80            // smem row stride bytes (32 bf16 = 64B data + 16B pad)
#define MATB (128 * SROW)  // 10240 B per matrix tile
#define SA_H 0
#define SA_L (1 * MATB)
#define SB_H (2 * MATB)
#define SB_L (3 * MATB)
#define STAGEB (4 * MATB)          // 40960
#define PS_OFF (2 * STAGEB)        // 81920
#define AR_OFF (PS_OFF + 512)
#define SMEM_TOTAL (AR_OFF + 512)  // 82944

__device__ int d_cnt[NE];
__device__ int d_bucket[NE][NP];
__device__ __nv_bfloat16 d_gh[(size_t)NP * ID];
__device__ __nv_bfloat16 d_gl[(size_t)NP * ID];

// ---------------- helpers ----------------
__device__ __forceinline__ uint32_t smem_u32(const void* p) {
    uint32_t a;
    asm("{ .reg .u64 t; cvta.to.shared.u64 t, %1; cvt.u32.u64 %0, t; }" : "=r"(a) : "l"(p));
    return a;
}
__device__ __forceinline__ void ldsm4(uint32_t* r, uint32_t a) {
    asm volatile("ldmatrix.sync.aligned.m8n8.x4.shared.b16 {%0,%1,%2,%3}, [%4];"
                 : "=r"(r[0]), "=r"(r[1]), "=r"(r[2]), "=r"(r[3]) : "r"(a));
}
__device__ __forceinline__ void mma16816(float* c, const uint32_t* a, uint32_t b0, uint32_t b1) {
    asm volatile("mma.sync.aligned.m16n8k16.row.col.f32.bf16.bf16.f32 "
                 "{%0,%1,%2,%3}, {%4,%5,%6,%7}, {%8,%9}, {%0,%1,%2,%3};"
                 : "+f"(c[0]), "+f"(c[1]), "+f"(c[2]), "+f"(c[3])
                 : "r"(a[0]), "r"(a[1]), "r"(a[2]), "r"(a[3]), "r"(b0), "r"(b1));
}
// fp32x4 -> bf16 hi (8B) + bf16 lo (8B)
__device__ __forceinline__ void split4(float4 v, uint2& h, uint2& l) {
    __nv_bfloat162 h01 = __floats2bfloat162_rn(v.x, v.y);
    __nv_bfloat162 h23 = __floats2bfloat162_rn(v.z, v.w);
    float2 f01 = __bfloat1622float2(h01);
    float2 f23 = __bfloat1622float2(h23);
    __nv_bfloat162 l01 = __floats2bfloat162_rn(v.x - f01.x, v.y - f01.y);
    __nv_bfloat162 l23 = __floats2bfloat162_rn(v.z - f23.x, v.w - f23.y);
    h.x = *(uint32_t*)&h01; h.y = *(uint32_t*)&h23;
    l.x = *(uint32_t*)&l01; l.y = *(uint32_t*)&l23;
}
__device__ __forceinline__ float swiglu_pair(float xg, float xl) {
    xg = fminf(xg, 7.0f);
    xl = fminf(fmaxf(xl, -7.0f), 7.0f);
    float s = 1.0f / (1.0f + __expf(-1.702f * xg));
    return xg * s * (xl + 1.0f);
}

__global__ void zero_cnt_kernel() {
    if (threadIdx.x < NE) d_cnt[threadIdx.x] = 0;
}
__global__ void scatter_kernel(const int* __restrict__ idx) {
    int p = blockIdx.x * blockDim.x + threadIdx.x;
    if (p < NP) {
        int e = idx[p];
        int pos = atomicAdd(&d_cnt[e], 1);
        d_bucket[e][pos] = p;
    }
}

// ---------------- shared compute core ----------------
// Per warp: 64(M) x 32(N), 16 m16n8k16 tiles, 3-term bf16.
// TERM-MAJOR issue order: 16 independent accumulators between revisits of the
// same acc -> no RAW stall on the tensor pipe (asm volatile fixes program order).
__device__ __forceinline__ void compute_stage(uint32_t sbase, uint32_t aoff, uint32_t boff,
                                              float acc[16][4]) {
#pragma unroll
    for (int kc = 0; kc < 2; ++kc) {
        uint32_t Ah[4][4], Al[4][4], Bh[2][4], Bl[2][4];
#pragma unroll
        for (int mt = 0; mt < 4; ++mt) {
            ldsm4(Ah[mt], sbase + SA_H + aoff + mt * 1280 + kc * 32);
            ldsm4(Al[mt], sbase + SA_L + aoff + mt * 1280 + kc * 32);
        }
#pragma unroll
        for (int nt2 = 0; nt2 < 2; ++nt2) {
            ldsm4(Bh[nt2], sbase + SB_H + boff + nt2 * 1280 + kc * 32);
            ldsm4(Bl[nt2], sbase + SB_L + boff + nt2 * 1280 + kc * 32);
        }
        // term 1: Ah * Bh
#pragma unroll
        for (int mt = 0; mt < 4; ++mt)
#pragma unroll
            for (int nt = 0; nt < 4; ++nt)
                mma16816(acc[mt * 4 + nt], Ah[mt],
                         Bh[nt >> 1][(nt & 1) * 2], Bh[nt >> 1][(nt & 1) * 2 + 1]);
        // term 2: Ah * Bl
#pragma unroll
        for (int mt = 0; mt < 4; ++mt)
#pragma unroll
            for (int nt = 0; nt < 4; ++nt)
                mma16816(acc[mt * 4 + nt], Ah[mt],
                         Bl[nt >> 1][(nt & 1) * 2], Bl[nt >> 1][(nt & 1) * 2 + 1]);
        // term 3: Al * Bh
#pragma unroll
        for (int mt = 0; mt < 4; ++mt)
#pragma unroll
            for (int nt = 0; nt < 4; ++nt)
                mma16816(acc[mt * 4 + nt], Al[mt],
                         Bh[nt >> 1][(nt & 1) * 2], Bh[nt >> 1][(nt & 1) * 2 + 1]);
    }
}

// ldmatrix per-thread offsets (within a stage's matrix tile)
__device__ __forceinline__ uint32_t a_ldsm_off(int wm, int lane) {
    return (uint32_t)(wm * 64 + (lane & 15)) * SROW + ((lane >> 4) * 16);
}
__device__ __forceinline__ uint32_t b_ldsm_off(int wn, int lane) {
    return (uint32_t)(wn * 32 + (lane & 7) + ((lane & 16) >> 1)) * SROW + ((lane & 8) * 2);
}

// ---------------- gate_up: g = swiglu(T_gather x W1^T + b1) -> d_gh/d_gl ----
__global__ __launch_bounds__(256, 1) void gate_kernel(
    const float* __restrict__ t, const float* __restrict__ w1,
    const float* __restrict__ b1) {
    const int e = blockIdx.z;
    const int M = d_cnt[e];
    const int m0 = blockIdx.x * BM;
    if (m0 >= M) return;
    const int n0 = blockIdx.y * BN;

    extern __shared__ char smem[];
    uint32_t su = smem_u32(smem);
    const int tid = threadIdx.x, lane = tid & 31, wid = tid >> 5;
    int* ps = (int*)(smem + PS_OFF);
    int* ar = (int*)(smem + AR_OFF);
    if (tid < BM) {
        int r = m0 + tid;
        int p = (r < M) ? d_bucket[e][r] : -1;
        ps[tid] = p;
        ar[tid] = (p >= 0) ? (p >> 2) : -1;
    }
    __syncthreads();

    // loader: 4 float4 chunks per matrix per thread (128 rows x 32 floats)
    uint32_t soff[4];
    const float* aP[4];
    const float* bP[4];
    bool avv[4];
    const float* wb = w1 + ((size_t)e * I2D + n0) * HD;
#pragma unroll
    for (int i = 0; i < 4; i++) {
        int c = tid + i * 256;
        int row = c >> 3, c8 = c & 7;
        soff[i] = (uint32_t)row * SROW + c8 * 8;
        int tok = ar[row];
        avv[i] = (tok >= 0);
        aP[i] = t + (size_t)(tok < 0 ? 0 : tok) * HD + c8 * 4;
        bP[i] = wb + (size_t)row * HD + c8 * 4;
    }

    const int wm = wid >> 2, wn = wid & 3;
    const uint32_t aoff = a_ldsm_off(wm, lane);
    const uint32_t boff = b_ldsm_off(wn, lane);

    float acc[16][4];
#pragma unroll
    for (int i = 0; i < 16; i++) { acc[i][0] = acc[i][1] = acc[i][2] = acc[i][3] = 0.f; }

    const float4 fz = make_float4(0.f, 0.f, 0.f, 0.f);
    float4 va[4], vb[4];
#pragma unroll
    for (int i = 0; i < 4; i++) {
        va[i] = avv[i] ? *(const float4*)(aP[i]) : fz;
        vb[i] = *(const float4*)(bP[i]);
    }
    {   // store stage 0
        char* st = smem;
#pragma unroll
        for (int i = 0; i < 4; i++) {
            uint2 h, l;
            split4(va[i], h, l);
            *(uint2*)(st + SA_H + soff[i]) = h; *(uint2*)(st + SA_L + soff[i]) = l;
            split4(vb[i], h, l);
            *(uint2*)(st + SB_H + soff[i]) = h; *(uint2*)(st + SB_L + soff[i]) = l;
        }
    }
    __syncthreads();

    for (int it = 0; it < NIT; ++it) {
        const int b = it & 1;
        if (it + 1 < NIT) {
            const int k0 = (it + 1) * KT;
#pragma unroll
            for (int i = 0; i < 4; i++) {
                va[i] = avv[i] ? *(const float4*)(aP[i] + k0) : fz;
                vb[i] = *(const float4*)(bP[i] + k0);
            }
        }
        compute_stage(su + b * STAGEB, aoff, boff, acc);
        __syncthreads();
        if (it + 1 < NIT) {
            char* st = smem + (b ^ 1) * STAGEB;
#pragma unroll
            for (int i = 0; i < 4; i++) {
                uint2 h, l;
                split4(va[i], h, l);
                *(uint2*)(st + SA_H + soff[i]) = h; *(uint2*)(st + SA_L + soff[i]) = l;
                split4(vb[i], h, l);
                *(uint2*)(st + SB_H + soff[i]) = h; *(uint2*)(st + SB_L + soff[i]) = l;
            }
            __syncthreads();
        }
    }

    // epilogue: bias + swiglu -> bf16 hi/lo activations
    const int g = lane >> 2, q = lane & 3;
    const float* bb = b1 + (size_t)e * I2D;
#pragma unroll
    for (int nt = 0; nt < 4; ++nt) {
        int n = n0 + wn * 32 + nt * 8 + q * 2;
        float bn0 = __ldg(bb + n), bn1 = __ldg(bb + n + 1);
#pragma unroll
        for (int mt = 0; mt < 4; ++mt) {
            float* c = acc[mt * 4 + nt];
            int r0 = wm * 64 + mt * 16 + g;
            if (m0 + r0 < M) {
                int p = ps[r0];
                float gg = swiglu_pair(c[0] + bn0, c[1] + bn1);
                __nv_bfloat16 h = __float2bfloat16(gg);
                __nv_bfloat16 lo = __float2bfloat16(gg - __bfloat162float(h));
                size_t o = (size_t)p * ID + (n >> 1);
                d_gh[o] = h; d_gl[o] = lo;
            }
            int r1 = r0 + 8;
            if (m0 + r1 < M) {
                int p = ps[r1];
                float gg = swiglu_pair(c[2] + bn0, c[3] + bn1);
                __nv_bfloat16 h = __float2bfloat16(gg);
                __nv_bfloat16 lo = __float2bfloat16(gg - __bfloat162float(h));
                size_t o = (size_t)p * ID + (n >> 1);
                d_gh[o] = h; d_gl[o] = lo;
            }
        }
    }
}

// ---------------- down: out = G x W2^T + b2 ----------------
__global__ __launch_bounds__(256, 1) void down_kernel(
    const float* __restrict__ w2, const float* __restrict__ b2,
    float* __restrict__ out) {
    const int e = blockIdx.z;
    const int M = d_cnt[e];
    const int m0 = blockIdx.x * BM;
    if (m0 >= M) return;
    const int n0 = blockIdx.y * BN;

    extern __shared__ char smem[];
    uint32_t su = smem_u32(smem);
    const int tid = threadIdx.x, lane = tid & 31, wid = tid >> 5;
    int* ps = (int*)(smem + PS_OFF);
    if (tid < BM) {
        int r = m0 + tid;
        ps[tid] = (r < M) ? d_bucket[e][r] : -1;
    }
    __syncthreads();

    // A loader: bf16 hi/lo, 2 x 16B chunks per thread per matrix
    uint32_t soffA[2];
    const uint4* ghP[2];
    const uint4* glP[2];
    bool avA[2];
#pragma unroll
    for (int i = 0; i < 2; i++) {
        int c = tid + i * 256;
        int row = c >> 2, c4 = c & 3;
        soffA[i] = (uint32_t)row * SROW + c4 * 16;
        int p = ps[row];
        avA[i] = (p >= 0);
        size_t off = (size_t)(p < 0 ? 0 : p) * ID + c4 * 8;
        ghP[i] = (const uint4*)(d_gh + off);
        glP[i] = (const uint4*)(d_gl + off);
    }
    // B loader: fp32 w2 with conversion
    uint32_t soffB[4];
    const float* bP[4];
    const float* wb = w2 + ((size_t)e * HD + n0) * ID;
#pragma unroll
    for (int i = 0; i < 4; i++) {
        int c = tid + i * 256;
        int row = c >> 3, c8 = c & 7;
        soffB[i] = (uint32_t)row * SROW + c8 * 8;
        bP[i] = wb + (size_t)row * ID + c8 * 4;
    }

    const int wm = wid >> 2, wn = wid & 3;
    const uint32_t aoff = a_ldsm_off(wm, lane);
    const uint32_t boff = b_ldsm_off(wn, lane);

    float acc[16][4];
#pragma unroll
    for (int i = 0; i < 16; i++) { acc[i][0] = acc[i][1] = acc[i][2] = acc[i][3] = 0.f; }

    const uint4 uz = make_uint4(0, 0, 0, 0);
    uint4 vah[2], val[2];
    float4 vb[4];
#pragma unroll
    for (int i = 0; i < 2; i++) {
        vah[i] = avA[i] ? __ldg(ghP[i]) : uz;
        val[i] = avA[i] ? __ldg(glP[i]) : uz;
    }
#pragma unroll
    for (int i = 0; i < 4; i++) vb[i] = *(const float4*)(bP[i]);
    {
        char* st = smem;
#pragma unroll
        for (int i = 0; i < 2; i++) {
            *(uint4*)(st + SA_H + soffA[i]) = vah[i];
            *(uint4*)(st + SA_L + soffA[i]) = val[i];
        }
#pragma unroll
        for (int i = 0; i < 4; i++) {
            uint2 h, l;
            split4(vb[i], h, l);
            *(uint2*)(st + SB_H + soffB[i]) = h; *(uint2*)(st + SB_L + soffB[i]) = l;
        }
    }
    __syncthreads();

    for (int it = 0; it < NIT; ++it) {
        const int b = it & 1;
        if (it + 1 < NIT) {
            const int k0 = (it + 1) * KT;   // elements (bf16 for A, fp32 for B)
#pragma unroll
            for (int i = 0; i < 2; i++) {
                vah[i] = avA[i] ? __ldg((const uint4*)((const __nv_bfloat16*)ghP[i] + k0)) : uz;
                val[i] = avA[i] ? __ldg((const uint4*)((const __nv_bfloat16*)glP[i] + k0)) : uz;
            }
#pragma unroll
            for (int i = 0; i < 4; i++) vb[i] = *(const float4*)(bP[i] + k0);
        }
        compute_stage(su + b * STAGEB, aoff, boff, acc);
        __syncthreads();
        if (it + 1 < NIT) {
            char* st = smem + (b ^ 1) * STAGEB;
#pragma unroll
            for (int i = 0; i < 2; i++) {
                *(uint4*)(st + SA_H + soffA[i]) = vah[i];
                *(uint4*)(st + SA_L + soffA[i]) = val[i];
            }
#pragma unroll
            for (int i = 0; i < 4; i++) {
                uint2 h, l;
                split4(vb[i], h, l);
                *(uint2*)(st + SB_H + soffB[i]) = h; *(uint2*)(st + SB_L + soffB[i]) = l;
            }
            __syncthreads();
        }
    }

    // epilogue: bias, fp32 out
    const int g = lane >> 2, q = lane & 3;
    const float* bb = b2 + (size_t)e * HD;
#pragma unroll
    for (int nt = 0; nt < 4; ++nt) {
        int n = n0 + wn * 32 + nt * 8 + q * 2;
        float bn0 = __ldg(bb + n), bn1 = __ldg(bb + n + 1);
#pragma unroll
        for (int mt = 0; mt < 4; ++mt) {
            float* c = acc[mt * 4 + nt];
            int r0 = wm * 64 + mt * 16 + g;
            if (m0 + r0 < M) {
                int p = ps[r0];
                float2 v = make_float2(c[0] + bn0, c[1] + bn1);
                *(float2*)(out + (size_t)p * HD + n) = v;
            }
            int r1 = r0 + 8;
            if (m0 + r1 < M) {
                int p = ps[r1];
                float2 v = make_float2(c[2] + bn0, c[3] + bn1);
                *(float2*)(out + (size_t)p * HD + n) = v;
            }
        }
    }
}

// ---------------- launch ----------------
extern "C" void kernel_launch(void* const* d_in, const int* in_sizes, int n_in,
                              void* d_out, int out_size) {
    const float* t   = (const float*)d_in[0];
    const int*   idx = (const int*)d_in[1];
    const float* w1  = (const float*)d_in[2];
    const float* b1  = (const float*)d_in[3];
    const float* w2  = (const float*)d_in[4];
    const float* b2  = (const float*)d_in[5];
    float* out = (float*)d_out;

    cudaFuncSetAttribute(gate_kernel, cudaFuncAttributeMaxDynamicSharedMemorySize, SMEM_TOTAL);
    cudaFuncSetAttribute(down_kernel, cudaFuncAttributeMaxDynamicSharedMemorySize, SMEM_TOTAL);

    zero_cnt_kernel<<<1, 32>>>();
    scatter_kernel<<<NP / 256, 256>>>(idx);
    gate_kernel<<<dim3(NP / BM, I2D / BN, NE), 256, SMEM_TOTAL>>>(t, w1, b1);
    down_kernel<<<dim3(NP / BM, HD / BN, NE), 256, SMEM_TOTAL>>>(w2, b2, out);
}